// round 16
// baseline (speedup 1.0000x reference)
#include <cuda_runtime.h>
#include <cstdint>

#define D_IN 64
#define D_E 64
#define D_OUT 128
#define MAX_NODES 50000

__device__ float g_hneigh[MAX_NODES * D_OUT];
// packed bf16 split rows for nfeats: per row 128B hi + 128B lo
__device__ __align__(16) unsigned char g_nconv[(size_t)MAX_NODES * 256];

// ============================ helpers ============================
__device__ __forceinline__ void red_add_v4(float* p, float a, float b, float c, float d) {
    asm volatile("red.global.add.v4.f32 [%0], {%1, %2, %3, %4};"
                 :: "l"(p), "f"(a), "f"(b), "f"(c), "f"(d) : "memory");
}
__device__ __forceinline__ uint32_t smem_u32(const void* p) {
    uint32_t a;
    asm("{ .reg .u64 t; cvta.to.shared.u64 t, %1; cvt.u32.u64 %0, t; }" : "=r"(a) : "l"(p));
    return a;
}
__device__ __forceinline__ void ldsm4(uint32_t* r, uint32_t addr) {
    asm volatile("ldmatrix.sync.aligned.m8n8.x4.shared.b16 {%0,%1,%2,%3}, [%4];"
                 : "=r"(r[0]), "=r"(r[1]), "=r"(r[2]), "=r"(r[3]) : "r"(addr));
}
__device__ __forceinline__ void mma_bf16(float* c, const uint32_t* a, uint32_t b0, uint32_t b1) {
    asm volatile("mma.sync.aligned.m16n8k16.row.col.f32.bf16.bf16.f32 "
                 "{%0,%1,%2,%3}, {%4,%5,%6,%7}, {%8,%9}, {%0,%1,%2,%3};"
                 : "+f"(c[0]), "+f"(c[1]), "+f"(c[2]), "+f"(c[3])
                 : "r"(a[0]), "r"(a[1]), "r"(a[2]), "r"(a[3]), "r"(b0), "r"(b1));
}
__device__ __forceinline__ void cpa16(uint32_t dst, const void* src) {
    asm volatile("cp.async.cg.shared.global [%0], [%1], 16;" :: "r"(dst), "l"(src));
}
#define CP_COMMIT() asm volatile("cp.async.commit_group;" ::: "memory")
#define CP_WAIT0()  asm volatile("cp.async.wait_group 0;" ::: "memory")
__device__ __forceinline__ void sts_zero16(uint32_t dst) {
    asm volatile("st.shared.v4.b32 [%0], {%1,%1,%1,%1};" :: "r"(dst), "r"(0u));
}
// convert 8 fp32 -> 4 bf16x2 hi + 4 bf16x2 lo
__device__ __forceinline__ void split8(float4 v0, float4 v1, uint32_t* h, uint32_t* l) {
    asm("cvt.rn.bf16x2.f32 %0, %1, %2;" : "=r"(h[0]) : "f"(v0.y), "f"(v0.x));
    asm("cvt.rn.bf16x2.f32 %0, %1, %2;" : "=r"(h[1]) : "f"(v0.w), "f"(v0.z));
    asm("cvt.rn.bf16x2.f32 %0, %1, %2;" : "=r"(h[2]) : "f"(v1.y), "f"(v1.x));
    asm("cvt.rn.bf16x2.f32 %0, %1, %2;" : "=r"(h[3]) : "f"(v1.w), "f"(v1.z));
    float r0 = v0.x - __uint_as_float(h[0] << 16);
    float r1 = v0.y - __uint_as_float(h[0] & 0xffff0000u);
    float r2 = v0.z - __uint_as_float(h[1] << 16);
    float r3 = v0.w - __uint_as_float(h[1] & 0xffff0000u);
    float r4 = v1.x - __uint_as_float(h[2] << 16);
    float r5 = v1.y - __uint_as_float(h[2] & 0xffff0000u);
    float r6 = v1.z - __uint_as_float(h[3] << 16);
    float r7 = v1.w - __uint_as_float(h[3] & 0xffff0000u);
    asm("cvt.rn.bf16x2.f32 %0, %1, %2;" : "=r"(l[0]) : "f"(r1), "f"(r0));
    asm("cvt.rn.bf16x2.f32 %0, %1, %2;" : "=r"(l[1]) : "f"(r3), "f"(r2));
    asm("cvt.rn.bf16x2.f32 %0, %1, %2;" : "=r"(l[2]) : "f"(r5), "f"(r4));
    asm("cvt.rn.bf16x2.f32 %0, %1, %2;" : "=r"(l[3]) : "f"(r7), "f"(r6));
}
#define STS128(addr, r) \
    asm volatile("st.shared.v4.b32 [%0], {%1,%2,%3,%4};" \
                 :: "r"(addr), "r"((r)[0]), "r"((r)[1]), "r"((r)[2]), "r"((r)[3]))

__global__ void zero_hneigh_kernel(int n4) {
    int i = blockIdx.x * blockDim.x + threadIdx.x;
    if (i < n4)
        reinterpret_cast<float4*>(g_hneigh)[i] = make_float4(0.f, 0.f, 0.f, 0.f);
}

// ---------- prepass: nfeats fp32 -> packed bf16 hi/lo rows (256B/row) ----------
__global__ void conv_split_kernel(const float4* __restrict__ in,
                                  unsigned char* __restrict__ out, int nchunks) {
    int i = blockIdx.x * blockDim.x + threadIdx.x;
    if (i >= nchunks) return;
    int row = i >> 4, q = i & 15;
    float4 v = in[i];
    uint32_t h01, h23;
    asm("cvt.rn.bf16x2.f32 %0, %1, %2;" : "=r"(h01) : "f"(v.y), "f"(v.x));
    asm("cvt.rn.bf16x2.f32 %0, %1, %2;" : "=r"(h23) : "f"(v.w), "f"(v.z));
    float hx = __uint_as_float(h01 << 16);
    float hy = __uint_as_float(h01 & 0xffff0000u);
    float hz = __uint_as_float(h23 << 16);
    float hw = __uint_as_float(h23 & 0xffff0000u);
    uint32_t l01, l23;
    asm("cvt.rn.bf16x2.f32 %0, %1, %2;" : "=r"(l01) : "f"(v.y - hy), "f"(v.x - hx));
    asm("cvt.rn.bf16x2.f32 %0, %1, %2;" : "=r"(l23) : "f"(v.w - hw), "f"(v.z - hz));
    unsigned char* o = out + (size_t)row * 256;
    *reinterpret_cast<uint2*>(o + q * 8)       = make_uint2(h01, h23);
    *reinterpret_cast<uint2*>(o + 128 + q * 8) = make_uint2(l01, l23);
}

// =====================================================================
// Edge kernel (R14 verbatim): R9 pipeline + in-kernel efeats conversion.
// 2 CTAs/SM x 256 thr, 64-edge tiles.
// =====================================================================
#define SM_WHI  0u
#define SM_WLO  32768u
#define SM_XHI  65536u
#define SM_XLO  81920u
#define SM_EST  98304u
#define SM_EDGE_BYTES 114688u

__device__ __forceinline__ uint32_t toff(int row, int kchunk) {
    return ((uint32_t)row << 8) + ((uint32_t)(kchunk ^ (row & 7)) << 4);
}

__global__ __launch_bounds__(256, 2)
void edge_msg_kernel(const float* __restrict__ efeats,
                     const float* __restrict__ Wmsg,
                     const float* __restrict__ bmsg,
                     const int* __restrict__ src,
                     const int* __restrict__ dst,
                     int E)
{
    extern __shared__ char smem[];
    const uint32_t sb = smem_u32(smem);
    const int tid  = threadIdx.x;
    const int lane = tid & 31;
    const int wid  = tid >> 5;

    for (int i = tid; i < 128 * 128; i += 256) {
        int n = i >> 7, k = i & 127;
        float w = Wmsg[k * 128 + n];
        uint32_t hb;
        asm("cvt.rn.bf16x2.f32 %0, %1, %2;" : "=r"(hb) : "f"(0.f), "f"(w));
        float hf = __uint_as_float(hb << 16);
        uint32_t lb;
        asm("cvt.rn.bf16x2.f32 %0, %1, %2;" : "=r"(lb) : "f"(0.f), "f"(w - hf));
        uint32_t off = toff(n, k >> 3) + (k & 7) * 2;
        *reinterpret_cast<uint16_t*>(smem + SM_WHI + off) = (uint16_t)hb;
        *reinterpret_cast<uint16_t*>(smem + SM_WLO + off) = (uint16_t)lb;
    }
    __syncthreads();

    const int g_r    = lane & 7;
    const int g_row  = (wid << 3) + g_r;
    const int g_half = (lane >> 3) & 1;
    const int g_quart = lane >> 4;

    const int mbase = (wid & 1) * 32;
    const int nbase = (wid >> 1) * 32;
    const int mrel  = lane & 15;
    const int khA   = lane >> 4;
    const int nrel  = (lane & 7) + ((lane >> 4) << 3);
    const int khB   = (lane >> 3) & 1;
    const uint32_t swzA = (uint32_t)(mrel & 7);
    const uint32_t swzB = (uint32_t)(nrel & 7);
    uint32_t aRow[2], bRow[2];
    #pragma unroll
    for (int mt = 0; mt < 2; ++mt) aRow[mt] = (uint32_t)(mbase + mt * 16 + mrel) << 8;
    #pragma unroll
    for (int g = 0; g < 2; ++g) bRow[g] = (uint32_t)(nbase + g * 16 + nrel) << 8;

    float bx[4], by[4];
    #pragma unroll
    for (int nt = 0; nt < 4; ++nt) {
        float2 bb = *reinterpret_cast<const float2*>(bmsg + nbase + nt * 8 + (lane & 3) * 2);
        bx[nt] = bb.x; by[nt] = bb.y;
    }

    float acc[2][4][4];
    #pragma unroll
    for (int mt = 0; mt < 2; ++mt)
        #pragma unroll
        for (int nt = 0; nt < 4; ++nt)
            #pragma unroll
            for (int q = 0; q < 4; ++q) acc[mt][nt][q] = 0.f;

    const uint32_t xhi = sb + SM_XHI, xlo = sb + SM_XLO;
    const uint32_t wHi = sb + SM_WHI, wLo = sb + SM_WLO;
    const uint32_t est = sb + SM_EST;

    const int cv_row = tid >> 2;
    const int cv_seg = tid & 3;
    const int cv_idx = cv_row * 16 + cv_seg * 4;
    const uint32_t cv_hi0 = xhi + toff(cv_row, 8 + 2 * cv_seg);
    const uint32_t cv_hi1 = xhi + toff(cv_row, 9 + 2 * cv_seg);
    const uint32_t cv_lo0 = xlo + toff(cv_row, 8 + 2 * cv_seg);
    const uint32_t cv_lo1 = xlo + toff(cv_row, 9 + 2 * cv_seg);

    const int tiles = (E + 63) >> 6;
    const int grid  = gridDim.x;

    auto issue_tile = [&](int base) {
        int sv = 0;
        {
            int ee = base + (wid << 3) + (lane & 7);
            if (lane < 8 && ee < E) sv = src[ee];
        }
        const int s  = __shfl_sync(0xffffffffu, sv, g_r);
        const int eg = base + g_row;
        const bool valid = (eg < E);
        if (g_half == 0) {
            const unsigned char* srow = g_nconv + (size_t)s * 256;
            #pragma unroll
            for (int c = 0; c < 4; ++c) {
                const int cl = (g_quart << 2) + c;
                const uint32_t dhi = xhi + toff(g_row, cl);
                const uint32_t dlo = xlo + toff(g_row, cl);
                if (valid) {
                    cpa16(dhi, srow + cl * 16);
                    cpa16(dlo, srow + 128 + cl * 16);
                } else {
                    sts_zero16(dhi);
                    sts_zero16(dlo);
                }
            }
        } else {
            const char* erow = reinterpret_cast<const char*>(efeats + (size_t)eg * D_E)
                             + g_quart * 128;
            const uint32_t eb = est + ((uint32_t)g_row << 8) + ((uint32_t)g_quart << 7);
            #pragma unroll
            for (int c = 0; c < 8; ++c) {
                if (valid) cpa16(eb + c * 16, erow + c * 16);
                else       sts_zero16(eb + c * 16);
            }
        }
    };

    int t = blockIdx.x;
    if (t < tiles) issue_tile(t << 6);
    CP_COMMIT();

    for (; t < tiles; t += grid) {
        CP_WAIT0();
        __syncthreads();

        {
            const float4* estp = reinterpret_cast<const float4*>(smem + SM_EST);
            float4 v0 = estp[cv_idx], v1 = estp[cv_idx + 1];
            float4 v2 = estp[cv_idx + 2], v3 = estp[cv_idx + 3];
            uint32_t h[4], l[4];
            split8(v0, v1, h, l);
            STS128(cv_hi0, h);
            STS128(cv_lo0, l);
            split8(v2, v3, h, l);
            STS128(cv_hi1, h);
            STS128(cv_lo1, l);
        }
        __syncthreads();

        const int base = t << 6;

        #pragma unroll
        for (int kc = 0; kc < 8; ++kc) {
            const uint32_t ka = (uint32_t)(((kc << 1) | khA) ^ swzA) << 4;
            const uint32_t kb = (uint32_t)(((kc << 1) | khB) ^ swzB) << 4;
            uint32_t ahi[2][4], alo[2][4], bfr[2][4];
            #pragma unroll
            for (int mt = 0; mt < 2; ++mt) ldsm4(ahi[mt], xhi + aRow[mt] + ka);
            #pragma unroll
            for (int mt = 0; mt < 2; ++mt) ldsm4(alo[mt], xlo + aRow[mt] + ka);
            #pragma unroll
            for (int g = 0; g < 2; ++g) ldsm4(bfr[g], wHi + bRow[g] + kb);
            #pragma unroll
            for (int mt = 0; mt < 2; ++mt)
                #pragma unroll
                for (int nt = 0; nt < 4; ++nt)
                    mma_bf16(acc[mt][nt], ahi[mt],
                             bfr[nt >> 1][(nt & 1) * 2], bfr[nt >> 1][(nt & 1) * 2 + 1]);
            #pragma unroll
            for (int mt = 0; mt < 2; ++mt)
                #pragma unroll
                for (int nt = 0; nt < 4; ++nt)
                    mma_bf16(acc[mt][nt], alo[mt],
                             bfr[nt >> 1][(nt & 1) * 2], bfr[nt >> 1][(nt & 1) * 2 + 1]);
            #pragma unroll
            for (int g = 0; g < 2; ++g) ldsm4(bfr[g], wLo + bRow[g] + kb);
            #pragma unroll
            for (int mt = 0; mt < 2; ++mt)
                #pragma unroll
                for (int nt = 0; nt < 4; ++nt)
                    mma_bf16(acc[mt][nt], ahi[mt],
                             bfr[nt >> 1][(nt & 1) * 2], bfr[nt >> 1][(nt & 1) * 2 + 1]);
        }

        __syncthreads();

        const int tn = t + grid;
        if (tn < tiles) issue_tile(tn << 6);
        CP_COMMIT();

        #pragma unroll
        for (int mt = 0; mt < 2; ++mt) {
            const int rtop = mbase + mt * 16 + (lane >> 2);
            const int etop = base + rtop;
            const int ebot = etop + 8;
            const int dtop = (etop < E) ? dst[etop] : 0;
            const int dbot = (ebot < E) ? dst[ebot] : 0;
            const int cb   = nbase + (lane & 2) * 2;
            #pragma unroll
            for (int nt = 0; nt < 4; ++nt) {
                float v0 = fmaxf(acc[mt][nt][0] + bx[nt], 0.f);
                float v1 = fmaxf(acc[mt][nt][1] + by[nt], 0.f);
                float v2 = fmaxf(acc[mt][nt][2] + bx[nt], 0.f);
                float v3 = fmaxf(acc[mt][nt][3] + by[nt], 0.f);
                float w0 = __shfl_xor_sync(0xffffffffu, v0, 1);
                float w1 = __shfl_xor_sync(0xffffffffu, v1, 1);
                float w2 = __shfl_xor_sync(0xffffffffu, v2, 1);
                float w3 = __shfl_xor_sync(0xffffffffu, v3, 1);
                if (!(lane & 1)) {
                    if (etop < E)
                        red_add_v4(g_hneigh + (size_t)dtop * D_OUT + cb + nt * 8, v0, v1, w0, w1);
                    if (ebot < E)
                        red_add_v4(g_hneigh + (size_t)dbot * D_OUT + cb + nt * 8, v2, v3, w2, w3);
                }
                acc[mt][nt][0] = 0.f; acc[mt][nt][1] = 0.f;
                acc[mt][nt][2] = 0.f; acc[mt][nt][3] = 0.f;
            }
        }
    }
}

// =====================================================================
// Apply kernel v4: R14 full-width apply + cp.async EST staging pipeline.
// Tile = 64 nodes x 128 cols, K=192.
// smem: Whi 48K | Wlo 48K | Xhi 24K | Xlo 24K | EST 48K | bias = 192.5KB
// =====================================================================
#define AP_WHI  0u
#define AP_WLO  49152u
#define AP_XHI  98304u
#define AP_XLO  122880u
#define AP_EST  147456u
#define AP_BIAS 196608u
#define AP_SMEM_BYTES 197120u

__device__ __forceinline__ uint32_t toffA(int row, int kchunk) {
    return (uint32_t)row * 384u + ((uint32_t)(kchunk ^ (row & 7)) << 4);
}

__global__ __launch_bounds__(256, 1)
void apply_mma_kernel(const float* __restrict__ nfeats,
                      const float* __restrict__ Wap,
                      const float* __restrict__ bap,
                      float* __restrict__ out,
                      int N)
{
    extern __shared__ char smem[];
    const uint32_t sb = smem_u32(smem);
    const int tid  = threadIdx.x;
    const int lane = tid & 31;
    const int wid  = tid >> 5;

    // ---- W split: Wt[n][k] = Wap[k][n] (k=0..191), bf16 hi/lo, swizzled ----
    for (int i = tid; i < 128 * 192; i += 256) {
        int n = i / 192, k = i % 192;
        float w = Wap[k * 128 + n];
        uint32_t hb;
        asm("cvt.rn.bf16x2.f32 %0, %1, %2;" : "=r"(hb) : "f"(0.f), "f"(w));
        float hf = __uint_as_float(hb << 16);
        uint32_t lb;
        asm("cvt.rn.bf16x2.f32 %0, %1, %2;" : "=r"(lb) : "f"(0.f), "f"(w - hf));
        uint32_t off = toffA(n, k >> 3) + (k & 7) * 2;
        *reinterpret_cast<uint16_t*>(smem + AP_WHI + off) = (uint16_t)hb;
        *reinterpret_cast<uint16_t*>(smem + AP_WLO + off) = (uint16_t)lb;
    }
    if (tid < 128) reinterpret_cast<float*>(smem + AP_BIAS)[tid] = bap[tid];
    __syncthreads();

    const int mbase = (wid & 1) * 32;
    const int nbase = (wid >> 1) * 32;
    const int mrel  = lane & 15;
    const int khA   = lane >> 4;
    const int nrel  = (lane & 7) + ((lane >> 4) << 3);
    const int khB   = (lane >> 3) & 1;
    const uint32_t swzA = (uint32_t)(mrel & 7);
    const uint32_t swzB = (uint32_t)(nrel & 7);
    uint32_t aRow[2], bRow[2];
    #pragma unroll
    for (int mt = 0; mt < 2; ++mt) aRow[mt] = (uint32_t)(mbase + mt * 16 + mrel) * 384u;
    #pragma unroll
    for (int g = 0; g < 2; ++g) bRow[g] = (uint32_t)(nbase + g * 16 + nrel) * 384u;

    float bx[4], by[4];
    {
        const float* bsm = reinterpret_cast<const float*>(smem + AP_BIAS);
        #pragma unroll
        for (int nt = 0; nt < 4; ++nt) {
            float2 bb = *reinterpret_cast<const float2*>(bsm + nbase + nt * 8 + (lane & 3) * 2);
            bx[nt] = bb.x; by[nt] = bb.y;
        }
    }

    // fill/convert mapping: 4 threads per row; each owns 6 kchunks (48B grain)
    const int f_row = tid >> 2;       // 0..63
    const int f_q   = tid & 3;

    const uint32_t xhi = sb + AP_XHI, xlo = sb + AP_XLO;
    const uint32_t wHi = sb + AP_WHI, wLo = sb + AP_WLO;
    const uint32_t est = sb + AP_EST;
    // EST: 768B per row, thread's 12 16B-chunks at f_q*192 .. +191
    const uint32_t est_t = est + (uint32_t)f_row * 768u + (uint32_t)f_q * 192u;

    float acc[2][4][4];
    #pragma unroll
    for (int mt = 0; mt < 2; ++mt)
        #pragma unroll
        for (int nt = 0; nt < 4; ++nt)
            #pragma unroll
            for (int q = 0; q < 4; ++q) acc[mt][nt][q] = 0.f;

    const int tiles = (N + 63) >> 6;
    const int grid  = gridDim.x;

    // cp.async [nfeats | h_neigh] row f_row into EST (12 x 16B per thread)
    auto issue_tile = [&](int base) {
        const int node = base + f_row;
        const bool valid = (node < N);
        const char* np = reinterpret_cast<const char*>(nfeats + (size_t)node * D_IN);
        const char* hp = reinterpret_cast<const char*>(g_hneigh + (size_t)node * D_OUT);
        #pragma unroll
        for (int c = 0; c < 12; ++c) {
            const int fc = f_q * 12 + c;        // 16B chunk index 0..47 within row
            const int col = fc * 4;             // starting float col
            const uint32_t d = est_t + c * 16;
            if (valid) {
                const char* sp = (col < D_IN) ? (np + col * 4)
                                              : (hp + (col - D_IN) * 4);
                cpa16(d, sp);
            } else {
                sts_zero16(d);
            }
        }
    };

    int t = blockIdx.x;
    if (t < tiles) issue_tile(t << 6);
    CP_COMMIT();

    for (; t < tiles; t += grid) {
        CP_WAIT0();
        __syncthreads();   // EST ready

        // ---- convert EST fp32 -> X hi/lo (6 kchunks of 8 floats per thread) ----
        {
            const float4* ep = reinterpret_cast<const float4*>(smem + AP_EST
                               + (uint32_t)f_row * 768u + (uint32_t)f_q * 192u);
            #pragma unroll
            for (int g = 0; g < 3; ++g) {
                float4 v0 = ep[g * 4 + 0], v1 = ep[g * 4 + 1];
                float4 v2 = ep[g * 4 + 2], v3 = ep[g * 4 + 3];
                const int kc0 = f_q * 6 + g * 2;
                uint32_t h[4], l[4];
                split8(v0, v1, h, l);
                STS128(xhi + toffA(f_row, kc0), h);
                STS128(xlo + toffA(f_row, kc0), l);
                split8(v2, v3, h, l);
                STS128(xhi + toffA(f_row, kc0 + 1), h);
                STS128(xlo + toffA(f_row, kc0 + 1), l);
            }
        }
        __syncthreads();   // X complete

        const int base = t << 6;

        // ---- MMA: Xhi*Whi + Xlo*Whi + Xhi*Wlo, K=192 (12 k16-chunks) ----
        #pragma unroll
        for (int kc = 0; kc < 12; ++kc) {
            const uint32_t ka = (uint32_t)(((kc << 1) | khA) ^ swzA) << 4;
            const uint32_t kb = (uint32_t)(((kc << 1) | khB) ^ swzB) << 4;
            uint32_t ahi[2][4], alo[2][4], bfr[2][4];
            #pragma unroll
            for (int mt = 0; mt < 2; ++mt) ldsm4(ahi[mt], xhi + aRow[mt] + ka);
            #pragma unroll
            for (int mt = 0; mt < 2; ++mt) ldsm4(alo[mt], xlo + aRow[mt] + ka);
            #pragma unroll
            for (int g = 0; g < 2; ++g) ldsm4(bfr[g], wHi + bRow[g] + kb);
            #pragma unroll
            for (int mt = 0; mt < 2; ++mt)
                #pragma unroll
                for (int nt = 0; nt < 4; ++nt)
                    mma_bf16(acc[mt][nt], ahi[mt],
                             bfr[nt >> 1][(nt & 1) * 2], bfr[nt >> 1][(nt & 1) * 2 + 1]);
            #pragma unroll
            for (int mt = 0; mt < 2; ++mt)
                #pragma unroll
                for (int nt = 0; nt < 4; ++nt)
                    mma_bf16(acc[mt][nt], alo[mt],
                             bfr[nt >> 1][(nt & 1) * 2], bfr[nt >> 1][(nt & 1) * 2 + 1]);
            #pragma unroll
            for (int g = 0; g < 2; ++g) ldsm4(bfr[g], wLo + bRow[g] + kb);
            #pragma unroll
            for (int mt = 0; mt < 2; ++mt)
                #pragma unroll
                for (int nt = 0; nt < 4; ++nt)
                    mma_bf16(acc[mt][nt], ahi[mt],
                             bfr[nt >> 1][(nt & 1) * 2], bfr[nt >> 1][(nt & 1) * 2 + 1]);
        }
        __syncthreads();   // EST/X reads done

        // issue next tile's EST gather — overlaps epilogue
        const int tn = t + grid;
        if (tn < tiles) issue_tile(tn << 6);
        CP_COMMIT();

        // ---- epilogue: bias+relu, pair-merge via shfl, float4 store ----
        #pragma unroll
        for (int mt = 0; mt < 2; ++mt) {
            const int rtop = mbase + mt * 16 + (lane >> 2);
            const int ntop = base + rtop;
            const int nbot = ntop + 8;
            const int cb   = nbase + (lane & 2) * 2;
            #pragma unroll
            for (int nt = 0; nt < 4; ++nt) {
                float v0 = fmaxf(acc[mt][nt][0] + bx[nt], 0.f);
                float v1 = fmaxf(acc[mt][nt][1] + by[nt], 0.f);
                float v2 = fmaxf(acc[mt][nt][2] + bx[nt], 0.f);
                float v3 = fmaxf(acc[mt][nt][3] + by[nt], 0.f);
                float w0 = __shfl_xor_sync(0xffffffffu, v0, 1);
                float w1 = __shfl_xor_sync(0xffffffffu, v1, 1);
                float w2 = __shfl_xor_sync(0xffffffffu, v2, 1);
                float w3 = __shfl_xor_sync(0xffffffffu, v3, 1);
                if (!(lane & 1)) {
                    if (ntop < N)
                        *reinterpret_cast<float4*>(out + (size_t)ntop * D_OUT + cb + nt * 8)
                            = make_float4(v0, v1, w0, w1);
                    if (nbot < N)
                        *reinterpret_cast<float4*>(out + (size_t)nbot * D_OUT + cb + nt * 8)
                            = make_float4(v2, v3, w2, w3);
                }
                acc[mt][nt][0] = 0.f; acc[mt][nt][1] = 0.f;
                acc[mt][nt][2] = 0.f; acc[mt][nt][3] = 0.f;
            }
        }
    }
}

extern "C" void kernel_launch(void* const* d_in, const int* in_sizes, int n_in,
                              void* d_out, int out_size)
{
    const float* nfeats = (const float*)d_in[0];
    const float* efeats = (const float*)d_in[1];
    const float* Wmsg   = (const float*)d_in[2];
    const float* bmsg   = (const float*)d_in[3];
    const float* Wap    = (const float*)d_in[4];
    const float* bap    = (const float*)d_in[5];
    const int*   src    = (const int*)d_in[6];
    const int*   dst    = (const int*)d_in[7];

    const int E = in_sizes[6];
    const int N = in_sizes[0] / D_IN;

    cudaFuncSetAttribute(edge_msg_kernel,  cudaFuncAttributeMaxDynamicSharedMemorySize, (int)SM_EDGE_BYTES);
    cudaFuncSetAttribute(apply_mma_kernel, cudaFuncAttributeMaxDynamicSharedMemorySize, (int)AP_SMEM_BYTES);

    unsigned char* nconv_p; cudaGetSymbolAddress((void**)&nconv_p, g_nconv);

    // prepass: nfeats only
    {
        int nchunks = N * 16;
        conv_split_kernel<<<(nchunks + 255) / 256, 256>>>(
            (const float4*)nfeats, nconv_p, nchunks);
    }

    const int n4 = (N * D_OUT) / 4;
    zero_hneigh_kernel<<<(n4 + 255) / 256, 256>>>(n4);
    edge_msg_kernel<<<296, 256, SM_EDGE_BYTES>>>(efeats, Wmsg, bmsg, src, dst, E);
    apply_mma_kernel<<<148, 256, AP_SMEM_BYTES>>>(nfeats, Wap, bap, (float*)d_out, N);
}

// round 17
// speedup vs baseline: 1.0074x; 1.0074x over previous
#include <cuda_runtime.h>
#include <cuda_fp16.h>
#include <cstdint>

#define D_IN 64
#define D_E 64
#define D_OUT 128
#define MAX_NODES 50000

__device__ float g_hneigh[MAX_NODES * D_OUT];
// packed bf16 split rows for nfeats: per row 128B hi + 128B lo
__device__ __align__(16) unsigned char g_nconv[(size_t)MAX_NODES * 256];

// ============================ helpers ============================
__device__ __forceinline__ void red_add_v4(float* p, float a, float b, float c, float d) {
    asm volatile("red.global.add.v4.f32 [%0], {%1, %2, %3, %4};"
                 :: "l"(p), "f"(a), "f"(b), "f"(c), "f"(d) : "memory");
}
__device__ __forceinline__ uint32_t smem_u32(const void* p) {
    uint32_t a;
    asm("{ .reg .u64 t; cvta.to.shared.u64 t, %1; cvt.u32.u64 %0, t; }" : "=r"(a) : "l"(p));
    return a;
}
__device__ __forceinline__ void ldsm4(uint32_t* r, uint32_t addr) {
    asm volatile("ldmatrix.sync.aligned.m8n8.x4.shared.b16 {%0,%1,%2,%3}, [%4];"
                 : "=r"(r[0]), "=r"(r[1]), "=r"(r[2]), "=r"(r[3]) : "r"(addr));
}
__device__ __forceinline__ void mma_bf16(float* c, const uint32_t* a, uint32_t b0, uint32_t b1) {
    asm volatile("mma.sync.aligned.m16n8k16.row.col.f32.bf16.bf16.f32 "
                 "{%0,%1,%2,%3}, {%4,%5,%6,%7}, {%8,%9}, {%0,%1,%2,%3};"
                 : "+f"(c[0]), "+f"(c[1]), "+f"(c[2]), "+f"(c[3])
                 : "r"(a[0]), "r"(a[1]), "r"(a[2]), "r"(a[3]), "r"(b0), "r"(b1));
}
__device__ __forceinline__ void mma_f16(float* c, const uint32_t* a, uint32_t b0, uint32_t b1) {
    asm volatile("mma.sync.aligned.m16n8k16.row.col.f32.f16.f16.f32 "
                 "{%0,%1,%2,%3}, {%4,%5,%6,%7}, {%8,%9}, {%0,%1,%2,%3};"
                 : "+f"(c[0]), "+f"(c[1]), "+f"(c[2]), "+f"(c[3])
                 : "r"(a[0]), "r"(a[1]), "r"(a[2]), "r"(a[3]), "r"(b0), "r"(b1));
}
__device__ __forceinline__ void cpa16(uint32_t dst, const void* src) {
    asm volatile("cp.async.cg.shared.global [%0], [%1], 16;" :: "r"(dst), "l"(src));
}
#define CP_COMMIT() asm volatile("cp.async.commit_group;" ::: "memory")
#define CP_WAIT0()  asm volatile("cp.async.wait_group 0;" ::: "memory")
__device__ __forceinline__ void sts_zero16(uint32_t dst) {
    asm volatile("st.shared.v4.b32 [%0], {%1,%1,%1,%1};" :: "r"(dst), "r"(0u));
}
// convert 8 fp32 -> 4 bf16x2 hi + 4 bf16x2 lo
__device__ __forceinline__ void split8(float4 v0, float4 v1, uint32_t* h, uint32_t* l) {
    asm("cvt.rn.bf16x2.f32 %0, %1, %2;" : "=r"(h[0]) : "f"(v0.y), "f"(v0.x));
    asm("cvt.rn.bf16x2.f32 %0, %1, %2;" : "=r"(h[1]) : "f"(v0.w), "f"(v0.z));
    asm("cvt.rn.bf16x2.f32 %0, %1, %2;" : "=r"(h[2]) : "f"(v1.y), "f"(v1.x));
    asm("cvt.rn.bf16x2.f32 %0, %1, %2;" : "=r"(h[3]) : "f"(v1.w), "f"(v1.z));
    float r0 = v0.x - __uint_as_float(h[0] << 16);
    float r1 = v0.y - __uint_as_float(h[0] & 0xffff0000u);
    float r2 = v0.z - __uint_as_float(h[1] << 16);
    float r3 = v0.w - __uint_as_float(h[1] & 0xffff0000u);
    float r4 = v1.x - __uint_as_float(h[2] << 16);
    float r5 = v1.y - __uint_as_float(h[2] & 0xffff0000u);
    float r6 = v1.z - __uint_as_float(h[3] << 16);
    float r7 = v1.w - __uint_as_float(h[3] & 0xffff0000u);
    asm("cvt.rn.bf16x2.f32 %0, %1, %2;" : "=r"(l[0]) : "f"(r1), "f"(r0));
    asm("cvt.rn.bf16x2.f32 %0, %1, %2;" : "=r"(l[1]) : "f"(r3), "f"(r2));
    asm("cvt.rn.bf16x2.f32 %0, %1, %2;" : "=r"(l[2]) : "f"(r5), "f"(r4));
    asm("cvt.rn.bf16x2.f32 %0, %1, %2;" : "=r"(l[3]) : "f"(r7), "f"(r6));
}
// convert 8 fp32 -> 4 f16x2 hi + 4 f16x2 lo
__device__ __forceinline__ void split8h(float4 v0, float4 v1, uint32_t* h, uint32_t* l) {
    __half2 h0 = __floats2half2_rn(v0.x, v0.y);
    __half2 h1 = __floats2half2_rn(v0.z, v0.w);
    __half2 h2 = __floats2half2_rn(v1.x, v1.y);
    __half2 h3 = __floats2half2_rn(v1.z, v1.w);
    h[0] = *reinterpret_cast<uint32_t*>(&h0);
    h[1] = *reinterpret_cast<uint32_t*>(&h1);
    h[2] = *reinterpret_cast<uint32_t*>(&h2);
    h[3] = *reinterpret_cast<uint32_t*>(&h3);
    __half2 l0 = __floats2half2_rn(v0.x - __half2float(__low2half(h0)),
                                   v0.y - __half2float(__high2half(h0)));
    __half2 l1 = __floats2half2_rn(v0.z - __half2float(__low2half(h1)),
                                   v0.w - __half2float(__high2half(h1)));
    __half2 l2 = __floats2half2_rn(v1.x - __half2float(__low2half(h2)),
                                   v1.y - __half2float(__high2half(h2)));
    __half2 l3 = __floats2half2_rn(v1.z - __half2float(__low2half(h3)),
                                   v1.w - __half2float(__high2half(h3)));
    l[0] = *reinterpret_cast<uint32_t*>(&l0);
    l[1] = *reinterpret_cast<uint32_t*>(&l1);
    l[2] = *reinterpret_cast<uint32_t*>(&l2);
    l[3] = *reinterpret_cast<uint32_t*>(&l3);
}
#define STS128(addr, r) \
    asm volatile("st.shared.v4.b32 [%0], {%1,%2,%3,%4};" \
                 :: "r"(addr), "r"((r)[0]), "r"((r)[1]), "r"((r)[2]), "r"((r)[3]))

// ---------- fused prepass: nfeats conv + zero g_hneigh ----------
__global__ void conv_zero_kernel(const float4* __restrict__ in,
                                 unsigned char* __restrict__ out,
                                 int nchunks, int n4) {
    int i = blockIdx.x * blockDim.x + threadIdx.x;
    if (i < nchunks) {
        int row = i >> 4, q = i & 15;
        float4 v = in[i];
        uint32_t h01, h23;
        asm("cvt.rn.bf16x2.f32 %0, %1, %2;" : "=r"(h01) : "f"(v.y), "f"(v.x));
        asm("cvt.rn.bf16x2.f32 %0, %1, %2;" : "=r"(h23) : "f"(v.w), "f"(v.z));
        float hx = __uint_as_float(h01 << 16);
        float hy = __uint_as_float(h01 & 0xffff0000u);
        float hz = __uint_as_float(h23 << 16);
        float hw = __uint_as_float(h23 & 0xffff0000u);
        uint32_t l01, l23;
        asm("cvt.rn.bf16x2.f32 %0, %1, %2;" : "=r"(l01) : "f"(v.y - hy), "f"(v.x - hx));
        asm("cvt.rn.bf16x2.f32 %0, %1, %2;" : "=r"(l23) : "f"(v.w - hw), "f"(v.z - hz));
        unsigned char* o = out + (size_t)row * 256;
        *reinterpret_cast<uint2*>(o + q * 8)       = make_uint2(h01, h23);
        *reinterpret_cast<uint2*>(o + 128 + q * 8) = make_uint2(l01, l23);
    }
    const int stride = gridDim.x * blockDim.x;
    for (int j = i; j < n4; j += stride)
        reinterpret_cast<float4*>(g_hneigh)[j] = make_float4(0.f, 0.f, 0.f, 0.f);
}

// =====================================================================
// Edge kernel (R14 verbatim): R9 pipeline + in-kernel efeats conversion.
// 2 CTAs/SM x 256 thr, 64-edge tiles.
// =====================================================================
#define SM_WHI  0u
#define SM_WLO  32768u
#define SM_XHI  65536u
#define SM_XLO  81920u
#define SM_EST  98304u
#define SM_EDGE_BYTES 114688u

__device__ __forceinline__ uint32_t toff(int row, int kchunk) {
    return ((uint32_t)row << 8) + ((uint32_t)(kchunk ^ (row & 7)) << 4);
}

__global__ __launch_bounds__(256, 2)
void edge_msg_kernel(const float* __restrict__ efeats,
                     const float* __restrict__ Wmsg,
                     const float* __restrict__ bmsg,
                     const int* __restrict__ src,
                     const int* __restrict__ dst,
                     int E)
{
    extern __shared__ char smem[];
    const uint32_t sb = smem_u32(smem);
    const int tid  = threadIdx.x;
    const int lane = tid & 31;
    const int wid  = tid >> 5;

    for (int i = tid; i < 128 * 128; i += 256) {
        int n = i >> 7, k = i & 127;
        float w = Wmsg[k * 128 + n];
        uint32_t hb;
        asm("cvt.rn.bf16x2.f32 %0, %1, %2;" : "=r"(hb) : "f"(0.f), "f"(w));
        float hf = __uint_as_float(hb << 16);
        uint32_t lb;
        asm("cvt.rn.bf16x2.f32 %0, %1, %2;" : "=r"(lb) : "f"(0.f), "f"(w - hf));
        uint32_t off = toff(n, k >> 3) + (k & 7) * 2;
        *reinterpret_cast<uint16_t*>(smem + SM_WHI + off) = (uint16_t)hb;
        *reinterpret_cast<uint16_t*>(smem + SM_WLO + off) = (uint16_t)lb;
    }
    __syncthreads();

    const int g_r    = lane & 7;
    const int g_row  = (wid << 3) + g_r;
    const int g_half = (lane >> 3) & 1;
    const int g_quart = lane >> 4;

    const int mbase = (wid & 1) * 32;
    const int nbase = (wid >> 1) * 32;
    const int mrel  = lane & 15;
    const int khA   = lane >> 4;
    const int nrel  = (lane & 7) + ((lane >> 4) << 3);
    const int khB   = (lane >> 3) & 1;
    const uint32_t swzA = (uint32_t)(mrel & 7);
    const uint32_t swzB = (uint32_t)(nrel & 7);
    uint32_t aRow[2], bRow[2];
    #pragma unroll
    for (int mt = 0; mt < 2; ++mt) aRow[mt] = (uint32_t)(mbase + mt * 16 + mrel) << 8;
    #pragma unroll
    for (int g = 0; g < 2; ++g) bRow[g] = (uint32_t)(nbase + g * 16 + nrel) << 8;

    float bx[4], by[4];
    #pragma unroll
    for (int nt = 0; nt < 4; ++nt) {
        float2 bb = *reinterpret_cast<const float2*>(bmsg + nbase + nt * 8 + (lane & 3) * 2);
        bx[nt] = bb.x; by[nt] = bb.y;
    }

    float acc[2][4][4];
    #pragma unroll
    for (int mt = 0; mt < 2; ++mt)
        #pragma unroll
        for (int nt = 0; nt < 4; ++nt)
            #pragma unroll
            for (int q = 0; q < 4; ++q) acc[mt][nt][q] = 0.f;

    const uint32_t xhi = sb + SM_XHI, xlo = sb + SM_XLO;
    const uint32_t wHi = sb + SM_WHI, wLo = sb + SM_WLO;
    const uint32_t est = sb + SM_EST;

    const int cv_row = tid >> 2;
    const int cv_seg = tid & 3;
    const int cv_idx = cv_row * 16 + cv_seg * 4;
    const uint32_t cv_hi0 = xhi + toff(cv_row, 8 + 2 * cv_seg);
    const uint32_t cv_hi1 = xhi + toff(cv_row, 9 + 2 * cv_seg);
    const uint32_t cv_lo0 = xlo + toff(cv_row, 8 + 2 * cv_seg);
    const uint32_t cv_lo1 = xlo + toff(cv_row, 9 + 2 * cv_seg);

    const int tiles = (E + 63) >> 6;
    const int grid  = gridDim.x;

    auto issue_tile = [&](int base) {
        int sv = 0;
        {
            int ee = base + (wid << 3) + (lane & 7);
            if (lane < 8 && ee < E) sv = src[ee];
        }
        const int s  = __shfl_sync(0xffffffffu, sv, g_r);
        const int eg = base + g_row;
        const bool valid = (eg < E);
        if (g_half == 0) {
            const unsigned char* srow = g_nconv + (size_t)s * 256;
            #pragma unroll
            for (int c = 0; c < 4; ++c) {
                const int cl = (g_quart << 2) + c;
                const uint32_t dhi = xhi + toff(g_row, cl);
                const uint32_t dlo = xlo + toff(g_row, cl);
                if (valid) {
                    cpa16(dhi, srow + cl * 16);
                    cpa16(dlo, srow + 128 + cl * 16);
                } else {
                    sts_zero16(dhi);
                    sts_zero16(dlo);
                }
            }
        } else {
            const char* erow = reinterpret_cast<const char*>(efeats + (size_t)eg * D_E)
                             + g_quart * 128;
            const uint32_t eb = est + ((uint32_t)g_row << 8) + ((uint32_t)g_quart << 7);
            #pragma unroll
            for (int c = 0; c < 8; ++c) {
                if (valid) cpa16(eb + c * 16, erow + c * 16);
                else       sts_zero16(eb + c * 16);
            }
        }
    };

    int t = blockIdx.x;
    if (t < tiles) issue_tile(t << 6);
    CP_COMMIT();

    for (; t < tiles; t += grid) {
        CP_WAIT0();
        __syncthreads();

        {
            const float4* estp = reinterpret_cast<const float4*>(smem + SM_EST);
            float4 v0 = estp[cv_idx], v1 = estp[cv_idx + 1];
            float4 v2 = estp[cv_idx + 2], v3 = estp[cv_idx + 3];
            uint32_t h[4], l[4];
            split8(v0, v1, h, l);
            STS128(cv_hi0, h);
            STS128(cv_lo0, l);
            split8(v2, v3, h, l);
            STS128(cv_hi1, h);
            STS128(cv_lo1, l);
        }
        __syncthreads();

        const int base = t << 6;

        #pragma unroll
        for (int kc = 0; kc < 8; ++kc) {
            const uint32_t ka = (uint32_t)(((kc << 1) | khA) ^ swzA) << 4;
            const uint32_t kb = (uint32_t)(((kc << 1) | khB) ^ swzB) << 4;
            uint32_t ahi[2][4], alo[2][4], bfr[2][4];
            #pragma unroll
            for (int mt = 0; mt < 2; ++mt) ldsm4(ahi[mt], xhi + aRow[mt] + ka);
            #pragma unroll
            for (int mt = 0; mt < 2; ++mt) ldsm4(alo[mt], xlo + aRow[mt] + ka);
            #pragma unroll
            for (int g = 0; g < 2; ++g) ldsm4(bfr[g], wHi + bRow[g] + kb);
            #pragma unroll
            for (int mt = 0; mt < 2; ++mt)
                #pragma unroll
                for (int nt = 0; nt < 4; ++nt)
                    mma_bf16(acc[mt][nt], ahi[mt],
                             bfr[nt >> 1][(nt & 1) * 2], bfr[nt >> 1][(nt & 1) * 2 + 1]);
            #pragma unroll
            for (int mt = 0; mt < 2; ++mt)
                #pragma unroll
                for (int nt = 0; nt < 4; ++nt)
                    mma_bf16(acc[mt][nt], alo[mt],
                             bfr[nt >> 1][(nt & 1) * 2], bfr[nt >> 1][(nt & 1) * 2 + 1]);
            #pragma unroll
            for (int g = 0; g < 2; ++g) ldsm4(bfr[g], wLo + bRow[g] + kb);
            #pragma unroll
            for (int mt = 0; mt < 2; ++mt)
                #pragma unroll
                for (int nt = 0; nt < 4; ++nt)
                    mma_bf16(acc[mt][nt], ahi[mt],
                             bfr[nt >> 1][(nt & 1) * 2], bfr[nt >> 1][(nt & 1) * 2 + 1]);
        }

        __syncthreads();

        const int tn = t + grid;
        if (tn < tiles) issue_tile(tn << 6);
        CP_COMMIT();

        #pragma unroll
        for (int mt = 0; mt < 2; ++mt) {
            const int rtop = mbase + mt * 16 + (lane >> 2);
            const int etop = base + rtop;
            const int ebot = etop + 8;
            const int dtop = (etop < E) ? dst[etop] : 0;
            const int dbot = (ebot < E) ? dst[ebot] : 0;
            const int cb   = nbase + (lane & 2) * 2;
            #pragma unroll
            for (int nt = 0; nt < 4; ++nt) {
                float v0 = fmaxf(acc[mt][nt][0] + bx[nt], 0.f);
                float v1 = fmaxf(acc[mt][nt][1] + by[nt], 0.f);
                float v2 = fmaxf(acc[mt][nt][2] + bx[nt], 0.f);
                float v3 = fmaxf(acc[mt][nt][3] + by[nt], 0.f);
                float w0 = __shfl_xor_sync(0xffffffffu, v0, 1);
                float w1 = __shfl_xor_sync(0xffffffffu, v1, 1);
                float w2 = __shfl_xor_sync(0xffffffffu, v2, 1);
                float w3 = __shfl_xor_sync(0xffffffffu, v3, 1);
                if (!(lane & 1)) {
                    if (etop < E)
                        red_add_v4(g_hneigh + (size_t)dtop * D_OUT + cb + nt * 8, v0, v1, w0, w1);
                    if (ebot < E)
                        red_add_v4(g_hneigh + (size_t)dbot * D_OUT + cb + nt * 8, v2, v3, w2, w3);
                }
                acc[mt][nt][0] = 0.f; acc[mt][nt][1] = 0.f;
                acc[mt][nt][2] = 0.f; acc[mt][nt][3] = 0.f;
            }
        }
    }
}

// =====================================================================
// Apply kernel v5: fp16 hi/lo, SINGLE W copy, 2 MMA passes, 2 CTAs/SM.
// Tile = 64 nodes x 128 cols, K=192.
// smem: W 48K | Xhi 24K | Xlo 24K | bias 0.5K = 98816B.
// =====================================================================
#define AP_W    0u
#define AP_XHI  49152u
#define AP_XLO  73728u
#define AP_BIAS 98304u
#define AP_SMEM_BYTES 98816u

__device__ __forceinline__ uint32_t toffA(int row, int kchunk) {
    return (uint32_t)row * 384u + ((uint32_t)(kchunk ^ (row & 7)) << 4);
}

__global__ __launch_bounds__(256, 2)
void apply_mma_kernel(const float* __restrict__ nfeats,
                      const float* __restrict__ Wap,
                      const float* __restrict__ bap,
                      float* __restrict__ out,
                      int N)
{
    extern __shared__ char smem[];
    const uint32_t sb = smem_u32(smem);
    const int tid  = threadIdx.x;
    const int lane = tid & 31;
    const int wid  = tid >> 5;

    // ---- W to smem: Wt[n][k] = fp16(Wap[k][n]) (k=0..191), swizzled ----
    for (int i = tid; i < 128 * 192; i += 256) {
        int n = i / 192, k = i % 192;
        __half wh = __float2half_rn(Wap[k * 128 + n]);
        uint32_t off = toffA(n, k >> 3) + (k & 7) * 2;
        *reinterpret_cast<__half*>(smem + AP_W + off) = wh;
    }
    if (tid < 128) reinterpret_cast<float*>(smem + AP_BIAS)[tid] = bap[tid];
    __syncthreads();

    const int mbase = (wid & 1) * 32;
    const int nbase = (wid >> 1) * 32;
    const int mrel  = lane & 15;
    const int khA   = lane >> 4;
    const int nrel  = (lane & 7) + ((lane >> 4) << 3);
    const int khB   = (lane >> 3) & 1;
    const uint32_t swzA = (uint32_t)(mrel & 7);
    const uint32_t swzB = (uint32_t)(nrel & 7);
    uint32_t aRow[2], bRow[2];
    #pragma unroll
    for (int mt = 0; mt < 2; ++mt) aRow[mt] = (uint32_t)(mbase + mt * 16 + mrel) * 384u;
    #pragma unroll
    for (int g = 0; g < 2; ++g) bRow[g] = (uint32_t)(nbase + g * 16 + nrel) * 384u;

    float bx[4], by[4];
    {
        const float* bsm = reinterpret_cast<const float*>(smem + AP_BIAS);
        #pragma unroll
        for (int nt = 0; nt < 4; ++nt) {
            float2 bb = *reinterpret_cast<const float2*>(bsm + nbase + nt * 8 + (lane & 3) * 2);
            bx[nt] = bb.x; by[nt] = bb.y;
        }
    }

    const int f_row = tid >> 2;
    const int f_q   = tid & 3;

    const uint32_t xhi = sb + AP_XHI, xlo = sb + AP_XLO;
    const uint32_t wS  = sb + AP_W;

    float acc[2][4][4];
    #pragma unroll
    for (int mt = 0; mt < 2; ++mt)
        #pragma unroll
        for (int nt = 0; nt < 4; ++nt)
            #pragma unroll
            for (int q = 0; q < 4; ++q) acc[mt][nt][q] = 0.f;

    const int tiles = (N + 63) >> 6;
    for (int t = blockIdx.x; t < tiles; t += gridDim.x) {
        const int base = t << 6;
        const int node = base + f_row;
        const bool valid = (node < N);

        // ---- fill X: [nfeats | h_neigh] fp32 -> fp16 hi/lo ----
        #pragma unroll
        for (int cc = 0; cc < 6; ++cc) {
            const int c = f_q * 6 + cc;
            float4 v0, v1;
            if (valid) {
                const int col = c * 8;
                const float* srcp = (c < 8)
                    ? (nfeats + (size_t)node * D_IN + col)
                    : (g_hneigh + (size_t)node * D_OUT + (col - D_IN));
                v0 = reinterpret_cast<const float4*>(srcp)[0];
                v1 = reinterpret_cast<const float4*>(srcp)[1];
            } else {
                v0 = make_float4(0.f, 0.f, 0.f, 0.f); v1 = v0;
            }
            uint32_t h[4], l[4];
            split8h(v0, v1, h, l);
            const uint32_t offc = toffA(f_row, c);
            STS128(xhi + offc, h);
            STS128(xlo + offc, l);
        }
        __syncthreads();

        // ---- MMA: Xhi*W + Xlo*W, K=192 (12 k16-chunks), single W ----
        #pragma unroll
        for (int kc = 0; kc < 12; ++kc) {
            const uint32_t ka = (uint32_t)(((kc << 1) | khA) ^ swzA) << 4;
            const uint32_t kb = (uint32_t)(((kc << 1) | khB) ^ swzB) << 4;
            uint32_t ahi[2][4], alo[2][4], bfr[2][4];
            #pragma unroll
            for (int mt = 0; mt < 2; ++mt) ldsm4(ahi[mt], xhi + aRow[mt] + ka);
            #pragma unroll
            for (int mt = 0; mt < 2; ++mt) ldsm4(alo[mt], xlo + aRow[mt] + ka);
            #pragma unroll
            for (int g = 0; g < 2; ++g) ldsm4(bfr[g], wS + bRow[g] + kb);
            #pragma unroll
            for (int mt = 0; mt < 2; ++mt)
                #pragma unroll
                for (int nt = 0; nt < 4; ++nt)
                    mma_f16(acc[mt][nt], ahi[mt],
                            bfr[nt >> 1][(nt & 1) * 2], bfr[nt >> 1][(nt & 1) * 2 + 1]);
            #pragma unroll
            for (int mt = 0; mt < 2; ++mt)
                #pragma unroll
                for (int nt = 0; nt < 4; ++nt)
                    mma_f16(acc[mt][nt], alo[mt],
                            bfr[nt >> 1][(nt & 1) * 2], bfr[nt >> 1][(nt & 1) * 2 + 1]);
        }
        __syncthreads();

        // ---- epilogue: bias+relu, pair-merge via shfl, float4 store ----
        #pragma unroll
        for (int mt = 0; mt < 2; ++mt) {
            const int rtop = mbase + mt * 16 + (lane >> 2);
            const int ntop = base + rtop;
            const int nbot = ntop + 8;
            const int cb   = nbase + (lane & 2) * 2;
            #pragma unroll
            for (int nt = 0; nt < 4; ++nt) {
                float v0 = fmaxf(acc[mt][nt][0] + bx[nt], 0.f);
                float v1 = fmaxf(acc[mt][nt][1] + by[nt], 0.f);
                float v2 = fmaxf(acc[mt][nt][2] + bx[nt], 0.f);
                float v3 = fmaxf(acc[mt][nt][3] + by[nt], 0.f);
                float w0 = __shfl_xor_sync(0xffffffffu, v0, 1);
                float w1 = __shfl_xor_sync(0xffffffffu, v1, 1);
                float w2 = __shfl_xor_sync(0xffffffffu, v2, 1);
                float w3 = __shfl_xor_sync(0xffffffffu, v3, 1);
                if (!(lane & 1)) {
                    if (ntop < N)
                        *reinterpret_cast<float4*>(out + (size_t)ntop * D_OUT + cb + nt * 8)
                            = make_float4(v0, v1, w0, w1);
                    if (nbot < N)
                        *reinterpret_cast<float4*>(out + (size_t)nbot * D_OUT + cb + nt * 8)
                            = make_float4(v2, v3, w2, w3);
                }
                acc[mt][nt][0] = 0.f; acc[mt][nt][1] = 0.f;
                acc[mt][nt][2] = 0.f; acc[mt][nt][3] = 0.f;
            }
        }
    }
}

extern "C" void kernel_launch(void* const* d_in, const int* in_sizes, int n_in,
                              void* d_out, int out_size)
{
    const float* nfeats = (const float*)d_in[0];
    const float* efeats = (const float*)d_in[1];
    const float* Wmsg   = (const float*)d_in[2];
    const float* bmsg   = (const float*)d_in[3];
    const float* Wap    = (const float*)d_in[4];
    const float* bap    = (const float*)d_in[5];
    const int*   src    = (const int*)d_in[6];
    const int*   dst    = (const int*)d_in[7];

    const int E = in_sizes[6];
    const int N = in_sizes[0] / D_IN;

    cudaFuncSetAttribute(edge_msg_kernel,  cudaFuncAttributeMaxDynamicSharedMemorySize, (int)SM_EDGE_BYTES);
    cudaFuncSetAttribute(apply_mma_kernel, cudaFuncAttributeMaxDynamicSharedMemorySize, (int)AP_SMEM_BYTES);

    unsigned char* nconv_p; cudaGetSymbolAddress((void**)&nconv_p, g_nconv);

    // fused prepass: nfeats conv + zero g_hneigh
    {
        int nchunks = N * 16;
        int n4 = (N * D_OUT) / 4;
        conv_zero_kernel<<<(nchunks + 255) / 256, 256>>>(
            (const float4*)nfeats, nconv_p, nchunks, n4);
    }

    edge_msg_kernel<<<296, 256, SM_EDGE_BYTES>>>(efeats, Wmsg, bmsg, src, dst, E);
    apply_mma_kernel<<<296, 256, AP_SMEM_BYTES>>>(nfeats, Wap, bap, (float*)d_out, N);
}